// round 15
// baseline (speedup 1.0000x reference)
#include <cuda_runtime.h>
#include <math.h>
#include <float.h>
#include <stdint.h>

#define NTOK  16384
#define BSZ   4
#define SEQ   4096
#define DIM   2048
#define NEXP  64
#define TOPK  8
#define BMT   108    // tokens per block; grid = 152 = #SMs -> exactly 1 block/SM
#define KC    64     // K chunk width (floats)
#define NCHUNK (DIM / KC)                // 32
#define NTH   384
#define NBLK  ((NTOK + BMT - 1) / BMT)   // 152
#define XSS   64     // xs row stride (floats)
#define LGS   66     // lg row stride (floats)
#define WK4   69     // wq4 k4-stride in float4 (proven layout)
#define WJ4   17     // wq4 j-stride in float4
#define WSLOTS 1024                      // w float4 slots per chunk
#define XSLOTS (BMT * 16)                // 1728 x float4 slots per chunk
#define WQF   (16 * WK4 * 4)             // floats per wq buffer: 4416
#define XSF   (BMT * XSS)                // floats per xs buffer: 6912
#define SMEM_DYN ((2 * WQF + 2 * XSF) * 4)   // 90624 B

#define FTZ_MIN 1.17549435e-38f   // FLT_MIN: fp32 normal threshold (FTZ cutoff)

__device__ float g_cnt[BSZ * NEXP];      // zero-init at load; re-zeroed by last block
__device__ float g_ssum[BSZ * NEXP];
__device__ unsigned g_done;

// Inner chunk compute: NT tokens at smem row row0, experts et*4..+3.
// K strictly ascending per accumulator (x->y->z->w): bitwise-stable fmaf chains.
template <int NT>
__device__ __forceinline__ void compute_chunk(
    const float* __restrict__ xs, const float4* __restrict__ wq4,
    int et, int row0, float (&acc)[5][4])
{
    #pragma unroll 2
    for (int k4 = 0; k4 < KC / 4; k4++) {
        float4 wv[4];
        #pragma unroll
        for (int j = 0; j < 4; j++)
            wv[j] = wq4[k4 * WK4 + j * WJ4 + et];
        float4 xv[NT];
        #pragma unroll
        for (int i = 0; i < NT; i++)
            xv[i] = *(const float4*)&xs[(row0 + i) * XSS + k4 * 4];

        #pragma unroll
        for (int i = 0; i < NT; i++)
            #pragma unroll
            for (int j = 0; j < 4; j++)
                acc[i][j] = fmaf(xv[i].x, wv[j].x, acc[i][j]);
        #pragma unroll
        for (int i = 0; i < NT; i++)
            #pragma unroll
            for (int j = 0; j < 4; j++)
                acc[i][j] = fmaf(xv[i].y, wv[j].y, acc[i][j]);
        #pragma unroll
        for (int i = 0; i < NT; i++)
            #pragma unroll
            for (int j = 0; j < 4; j++)
                acc[i][j] = fmaf(xv[i].z, wv[j].z, acc[i][j]);
        #pragma unroll
        for (int i = 0; i < NT; i++)
            #pragma unroll
            for (int j = 0; j < 4; j++)
                acc[i][j] = fmaf(xv[i].w, wv[j].w, acc[i][j]);
    }
}

__global__ __launch_bounds__(NTH, 1) void gate_main(
    const float* __restrict__ x, const float* __restrict__ w,
    const float* __restrict__ bias, float* __restrict__ out)
{
    extern __shared__ __align__(16) float dsm[];
    // layout: wqA | wqB | xsA | xsB ; lg/red overlay xsA..(contiguous, 13824 floats)
    float4* wqbuf[2] = { (float4*)dsm, (float4*)(dsm + WQF) };
    float*  xsbuf[2] = { dsm + 2 * WQF, dsm + 2 * WQF + XSF };
    float*  lg  = dsm + 2 * WQF;          // 108*66 = 7128 <= 13824
    float*  red = dsm + 2 * WQF;

    __shared__ float s_max[BMT];
    __shared__ float s_inv[BMT];
    __shared__ float s_cnt[2 * NEXP];
    __shared__ unsigned s_last;

    const int tid = threadIdx.x;
    const int et  = tid & 15;    // experts et*4 .. et*4+3
    const int ts  = tid >> 4;    // token slot 0..23
    const int nt  = (ts < 12) ? 5 : 4;
    const int row0 = (ts < 12) ? ts * 5 : 60 + (ts - 12) * 4;   // 12*5 + 12*4 = 108
    const int base = blockIdx.x * BMT;
    const int nval = min(BMT, NTOK - base);

    float acc[5][4];
    #pragma unroll
    for (int i = 0; i < 5; i++)
        #pragma unroll
        for (int j = 0; j < 4; j++) acc[i][j] = 0.f;

    float4 wr[3], xr[5];

    // ---- prefetch chunk 0 -> regs ----
    #pragma unroll
    for (int it = 0; it < 3; it++) {
        int idx = tid + it * NTH;
        if (idx < WSLOTS) {
            int r = idx >> 4, c = (idx & 15) << 2;
            wr[it] = *(const float4*)(w + (size_t)r * DIM + c);
        }
    }
    #pragma unroll
    for (int it = 0; it < 5; it++) {
        int idx = tid + it * NTH;
        if (idx < XSLOTS) {
            int r = idx >> 4, c = (idx & 15) << 2;
            int rr = min(base + r, NTOK - 1);      // clamp (last block partial)
            xr[it] = *(const float4*)(x + (size_t)rr * DIM + c);
        }
    }
    // store chunk 0 -> buffer 0
    #pragma unroll
    for (int it = 0; it < 3; it++) {
        int idx = tid + it * NTH;
        if (idx < WSLOTS) {
            int r = idx >> 4, c = (idx & 15) << 2;
            wqbuf[0][(c >> 2) * WK4 + (r & 3) * WJ4 + (r >> 2)] = wr[it];
        }
    }
    #pragma unroll
    for (int it = 0; it < 5; it++) {
        int idx = tid + it * NTH;
        if (idx < XSLOTS) {
            int r = idx >> 4, c = (idx & 15) << 2;
            *(float4*)&xsbuf[0][r * XSS + c] = xr[it];
        }
    }
    __syncthreads();
    // prefetch chunk 1 -> regs (lands during compute of chunk 0)
    #pragma unroll
    for (int it = 0; it < 3; it++) {
        int idx = tid + it * NTH;
        if (idx < WSLOTS) {
            int r = idx >> 4, c = (idx & 15) << 2;
            wr[it] = *(const float4*)(w + (size_t)r * DIM + KC + c);
        }
    }
    #pragma unroll
    for (int it = 0; it < 5; it++) {
        int idx = tid + it * NTH;
        if (idx < XSLOTS) {
            int r = idx >> 4, c = (idx & 15) << 2;
            int rr = min(base + r, NTOK - 1);
            xr[it] = *(const float4*)(x + (size_t)rr * DIM + KC + c);
        }
    }

    for (int c = 0; c < NCHUNK; c++) {
        // compute chunk c (warp-uniform branch: warps 0-5 NT=5, 6-11 NT=4)
        if (ts < 12) compute_chunk<5>(xsbuf[c & 1], wqbuf[c & 1], et, row0, acc);
        else         compute_chunk<4>(xsbuf[c & 1], wqbuf[c & 1], et, row0, acc);

        if (c + 1 < NCHUNK) {
            // store chunk c+1 (regs) -> other buffer; safe: all warps passed
            // sync(c-1) => finished compute(c-1) which read this buffer
            int nb = (c + 1) & 1;
            #pragma unroll
            for (int it = 0; it < 3; it++) {
                int idx = tid + it * NTH;
                if (idx < WSLOTS) {
                    int r = idx >> 4, cc = (idx & 15) << 2;
                    wqbuf[nb][(cc >> 2) * WK4 + (r & 3) * WJ4 + (r >> 2)] = wr[it];
                }
            }
            #pragma unroll
            for (int it = 0; it < 5; it++) {
                int idx = tid + it * NTH;
                if (idx < XSLOTS) {
                    int r = idx >> 4, cc = (idx & 15) << 2;
                    *(float4*)&xsbuf[nb][r * XSS + cc] = xr[it];
                }
            }
            __syncthreads();
            // issue LDG for chunk c+2 (lands during compute of c+1)
            if (c + 2 < NCHUNK) {
                int kofs = (c + 2) * KC;
                #pragma unroll
                for (int it = 0; it < 3; it++) {
                    int idx = tid + it * NTH;
                    if (idx < WSLOTS) {
                        int r = idx >> 4, cc = (idx & 15) << 2;
                        wr[it] = *(const float4*)(w + (size_t)r * DIM + kofs + cc);
                    }
                }
                #pragma unroll
                for (int it = 0; it < 5; it++) {
                    int idx = tid + it * NTH;
                    if (idx < XSLOTS) {
                        int r = idx >> 4, cc = (idx & 15) << 2;
                        int rr = min(base + r, NTOK - 1);
                        xr[it] = *(const float4*)(x + (size_t)rr * DIM + kofs + cc);
                    }
                }
            }
        }
    }
    __syncthreads();   // all xs/wq reads done before lg overwrites the overlay

    // logits + bias -> lg
    #pragma unroll
    for (int j = 0; j < 4; j++) {
        float b = bias[et * 4 + j];
        for (int i = 0; i < nt; i++)
            lg[(row0 + i) * LGS + et * 4 + j] = acc[i][j] + b;
    }
    if (tid < 2 * NEXP) s_cnt[tid] = 0.f;
    __syncthreads();

    const int b0 = base / SEQ;
    const int t_split = min(BMT, (b0 + 1) * SEQ - base);   // batch boundary in block

    // per-token softmax (FTZ) + top-8 on SCORES, ties -> lower index (lax.top_k)
    if (tid < nval) {
        const int t = tid;
        const float* lrow = &lg[t * LGS];
        float m = -FLT_MAX;
        for (int e = 0; e < NEXP; e++) m = fmaxf(m, lrow[e]);

        float sum = 0.f;
        for (int e = 0; e < NEXP; e++) {
            float s = expf(lrow[e] - m);
            if (s < FTZ_MIN) s = 0.f;
            sum += s;
        }
        float inv_sum = 1.f / sum;

        float bv[TOPK]; int bi[TOPK];
        #pragma unroll
        for (int r = 0; r < TOPK; r++) { bv[r] = -FLT_MAX; bi[r] = 0; }

        for (int e = 0; e < NEXP; e++) {
            float s = expf(lrow[e] - m);
            if (s < FTZ_MIN) s = 0.f;
            float q = s * inv_sum;
            if (q < FTZ_MIN) q = 0.f;
            if (q > bv[TOPK - 1]) {
                int p = TOPK - 1;
                while (p > 0 && q > bv[p - 1]) {
                    bv[p] = bv[p - 1]; bi[p] = bi[p - 1]; p--;
                }
                bv[p] = q; bi[p] = e;
            }
        }
        s_max[t] = m;
        s_inv[t] = inv_sum;

        float den = 1e-20f;
        #pragma unroll
        for (int r = 0; r < TOPK; r++) den += bv[r];
        float inv = 1.f / den;

        const int token = base + t;
        const int part  = (t < t_split) ? 0 : 1;
        #pragma unroll
        for (int r = 0; r < TOPK; r++)
            out[(size_t)token * TOPK + r] = (float)bi[r];
        #pragma unroll
        for (int r = 0; r < TOPK; r++)
            out[(size_t)NTOK * TOPK + (size_t)token * TOPK + r] = bv[r] * inv;
        #pragma unroll
        for (int r = 0; r < TOPK; r++)
            atomicAdd(&s_cnt[part * NEXP + bi[r]], 1.f);
    }
    __syncthreads();

    // per-expert column sums of (flushed) softmax scores, split by batch bucket
    if (tid < NEXP) {
        const int e = tid;
        float cs0 = 0.f, cs1 = 0.f;
        for (int t = 0; t < nval; t++) {
            float s = expf(lg[t * LGS + e] - s_max[t]);
            if (s < FTZ_MIN) s = 0.f;
            float q = s * s_inv[t];
            if (q < FTZ_MIN) q = 0.f;
            if (t < t_split) cs0 += q; else cs1 += q;
        }
        atomicAdd(&g_ssum[b0 * NEXP + e], cs0);
        atomicAdd(&g_cnt [b0 * NEXP + e], s_cnt[e]);
        if (t_split < nval) {
            atomicAdd(&g_ssum[(b0 + 1) * NEXP + e], cs1);
            atomicAdd(&g_cnt [(b0 + 1) * NEXP + e], s_cnt[NEXP + e]);
        }
    }

    // ---- fused finalize: last block computes aux, then resets globals ----
    __threadfence();
    __syncthreads();
    if (tid == 0)
        s_last = (atomicAdd(&g_done, 1u) == (unsigned)(NBLK - 1));
    __syncthreads();

    if (s_last) {
        // aux = mean_b sum_e (cnt/(SEQ*K/E)) * (ssum/SEQ)
        if (tid < 256)
            red[tid] = (g_cnt[tid] * (1.f / 512.f)) * (g_ssum[tid] * (1.f / 4096.f));
        __syncthreads();
        for (int s = 128; s > 0; s >>= 1) {
            if (tid < s) red[tid] += red[tid + s];
            __syncthreads();
        }
        if (tid == 0) out[2 * NTOK * TOPK] = red[0] * (1.f / BSZ);
        // reset for next graph replay
        if (tid < 256) { g_cnt[tid] = 0.f; g_ssum[tid] = 0.f; }
        if (tid == 0) g_done = 0u;
    }
}

extern "C" void kernel_launch(void* const* d_in, const int* in_sizes, int n_in,
                              void* d_out, int out_size) {
    const float* x    = (const float*)d_in[0];   // [4,4096,2048] f32
    const float* wgt  = (const float*)d_in[1];   // [64,2048]     f32
    const float* bias = (const float*)d_in[2];   // [64]          f32
    float* out = (float*)d_out;                  // [idx 131072][w 131072][aux 1]

    cudaFuncSetAttribute(gate_main, cudaFuncAttributeMaxDynamicSharedMemorySize,
                         SMEM_DYN);
    gate_main<<<NBLK, NTH, SMEM_DYN>>>(x, wgt, bias, out);
}

// round 17
// speedup vs baseline: 1.3139x; 1.3139x over previous
#include <cuda_runtime.h>
#include <math.h>
#include <float.h>
#include <stdint.h>

#define NTOK  16384
#define BSZ   4
#define SEQ   4096
#define DIM   2048
#define NEXP  64
#define TOPK  8
#define BMT   108    // tokens per block; grid = 152 = #SMs -> exactly 1 block/SM
#define KC    64     // K chunk width (floats)
#define NCHUNK (DIM / KC)                // 32
#define NTH   256
#define NBLK  ((NTOK + BMT - 1) / BMT)   // 152
#define XSS   64     // xs row stride (floats)
#define LGS   66     // lg row stride (floats)
#define WK4   69     // wq4 k4-stride in float4 (proven layout)
#define WJ4   17     // wq4 j-stride in float4
#define XSLOTS (BMT * 16)                // 1728 x float4 slots per chunk
#define WQF   (16 * WK4 * 4)             // floats per wq buffer: 4416
#define XSF   (BMT * XSS)                // floats per xs buffer: 6912
#define SMEM_DYN ((2 * WQF + 2 * XSF) * 4)   // 90624 B

#define FTZ_MIN 1.17549435e-38f   // FLT_MIN: fp32 normal threshold (FTZ cutoff)

__device__ float g_cnt[BSZ * NEXP];      // zero-init at load; re-zeroed by last block
__device__ float g_ssum[BSZ * NEXP];
__device__ unsigned g_done;

// Inner chunk compute: NT tokens at smem row row0, experts et*4..+3.
// K strictly ascending per accumulator (x->y->z->w): bitwise-stable fmaf chains.
template <int NT>
__device__ __forceinline__ void compute_chunk(
    const float* __restrict__ xs, const float4* __restrict__ wq4,
    int et, int row0, float (&acc)[7][4])
{
    #pragma unroll 2
    for (int k4 = 0; k4 < KC / 4; k4++) {
        float4 wv[4];
        #pragma unroll
        for (int j = 0; j < 4; j++)
            wv[j] = wq4[k4 * WK4 + j * WJ4 + et];
        float4 xv[NT];
        #pragma unroll
        for (int i = 0; i < NT; i++)
            xv[i] = *(const float4*)&xs[(row0 + i) * XSS + k4 * 4];

        #pragma unroll
        for (int i = 0; i < NT; i++)
            #pragma unroll
            for (int j = 0; j < 4; j++)
                acc[i][j] = fmaf(xv[i].x, wv[j].x, acc[i][j]);
        #pragma unroll
        for (int i = 0; i < NT; i++)
            #pragma unroll
            for (int j = 0; j < 4; j++)
                acc[i][j] = fmaf(xv[i].y, wv[j].y, acc[i][j]);
        #pragma unroll
        for (int i = 0; i < NT; i++)
            #pragma unroll
            for (int j = 0; j < 4; j++)
                acc[i][j] = fmaf(xv[i].z, wv[j].z, acc[i][j]);
        #pragma unroll
        for (int i = 0; i < NT; i++)
            #pragma unroll
            for (int j = 0; j < 4; j++)
                acc[i][j] = fmaf(xv[i].w, wv[j].w, acc[i][j]);
    }
}

__global__ __launch_bounds__(NTH, 1) void gate_main(
    const float* __restrict__ x, const float* __restrict__ w,
    const float* __restrict__ bias, float* __restrict__ out)
{
    extern __shared__ __align__(16) float dsm[];
    // layout: wq0 | wq1 | xs0 | xs1 ; lg/red overlay xs0.. (13824 floats available)
    float4* const wq0 = (float4*)dsm;
    float4* const wq1 = (float4*)(dsm + WQF);
    float*  const xs0 = dsm + 2 * WQF;
    float*  const xs1 = dsm + 2 * WQF + XSF;
    float*  const lg  = dsm + 2 * WQF;    // 108*66 = 7128 <= 13824
    float*  const red = dsm + 2 * WQF;

    __shared__ float s_max[BMT];
    __shared__ float s_inv[BMT];
    __shared__ float s_cnt[2 * NEXP];
    __shared__ unsigned s_last;

    const int tid = threadIdx.x;
    const int et  = tid & 15;    // experts et*4 .. et*4+3
    const int ts  = tid >> 4;    // token slot
    const int nt  = (ts < 12) ? 7 : 6;
    const int row0 = (ts < 12) ? ts * 7 : 84 + (ts - 12) * 6;   // 12*7 + 4*6 = 108
    const int base = blockIdx.x * BMT;
    const int nval = min(BMT, NTOK - base);

    float acc[7][4];
    #pragma unroll
    for (int i = 0; i < 7; i++)
        #pragma unroll
        for (int j = 0; j < 4; j++) acc[i][j] = 0.f;

    float4 wr[4], xr[7];

    // ---- hygienic prefetch macros: internal names _it/_ix/_r/_c cannot
    //      capture the caller's chunk variable used in the kofs argument ----
    #define LDG_CHUNK(kofs)                                                    \
        do {                                                                   \
            _Pragma("unroll")                                                  \
            for (int _it = 0; _it < 4; _it++) {                                \
                int _ix = tid + _it * NTH;                                     \
                int _r = _ix >> 4, _c = (_ix & 15) << 2;                       \
                wr[_it] = *(const float4*)(w + (size_t)_r * DIM + (kofs) + _c);\
            }                                                                  \
            _Pragma("unroll")                                                  \
            for (int _it = 0; _it < 7; _it++) {                                \
                int _ix = tid + _it * NTH;                                     \
                if (_ix < XSLOTS) {                                            \
                    int _r = _ix >> 4, _c = (_ix & 15) << 2;                   \
                    int _rr = min(base + _r, NTOK - 1);                        \
                    xr[_it] = *(const float4*)(x + (size_t)_rr * DIM + (kofs) + _c); \
                }                                                              \
            }                                                                  \
        } while (0)

    #define STS_CHUNK(wqb, xsb)                                                \
        do {                                                                   \
            _Pragma("unroll")                                                  \
            for (int _it = 0; _it < 4; _it++) {                                \
                int _ix = tid + _it * NTH;                                     \
                int _r = _ix >> 4, _c = (_ix & 15) << 2;                       \
                (wqb)[(_c >> 2) * WK4 + (_r & 3) * WJ4 + (_r >> 2)] = wr[_it]; \
            }                                                                  \
            _Pragma("unroll")                                                  \
            for (int _it = 0; _it < 7; _it++) {                                \
                int _ix = tid + _it * NTH;                                     \
                if (_ix < XSLOTS) {                                            \
                    int _r = _ix >> 4, _c = (_ix & 15) << 2;                   \
                    *(float4*)&(xsb)[_r * XSS + _c] = xr[_it];                 \
                }                                                              \
            }                                                                  \
        } while (0)

    #define COMPUTE(wqb, xsb)                                                  \
        do {                                                                   \
            if (ts < 12) compute_chunk<7>((xsb), (wqb), et, row0, acc);        \
            else         compute_chunk<6>((xsb), (wqb), et, row0, acc);        \
        } while (0)

    // prologue: chunk 0 -> buf0; chunk 1 -> regs
    LDG_CHUNK(0);
    STS_CHUNK(wq0, xs0);
    LDG_CHUNK(KC);

    // steady state: one sync per chunk, compile-time buffer selection
    for (int c = 0; c < NCHUNK; c += 2) {
        // chunk c (even, data in buf0); regs hold chunk c+1
        __syncthreads();               // compute(c-1)[buf1] done; store(c)[buf0] visible
        STS_CHUNK(wq1, xs1);           // store chunk c+1
        if (c + 2 < NCHUNK) LDG_CHUNK((c + 2) * KC);
        COMPUTE(wq0, xs0);

        // chunk c+1 (odd, data in buf1); regs hold chunk c+2
        __syncthreads();               // compute(c)[buf0] done; store(c+1)[buf1] visible
        if (c + 2 < NCHUNK) {
            STS_CHUNK(wq0, xs0);       // store chunk c+2
            if (c + 3 < NCHUNK) LDG_CHUNK((c + 3) * KC);
        }
        COMPUTE(wq1, xs1);
    }
    __syncthreads();   // all buffer reads done before lg overwrites the overlay

    // logits + bias -> lg
    #pragma unroll
    for (int j = 0; j < 4; j++) {
        float b = bias[et * 4 + j];
        for (int i = 0; i < nt; i++)
            lg[(row0 + i) * LGS + et * 4 + j] = acc[i][j] + b;
    }
    if (tid < 2 * NEXP) s_cnt[tid] = 0.f;
    __syncthreads();

    const int b0 = base / SEQ;
    const int t_split = min(BMT, (b0 + 1) * SEQ - base);   // batch boundary in block

    // per-token softmax (FTZ) + top-8 on SCORES, ties -> lower index (lax.top_k)
    if (tid < nval) {
        const int t = tid;
        const float* lrow = &lg[t * LGS];
        float m = -FLT_MAX;
        for (int e = 0; e < NEXP; e++) m = fmaxf(m, lrow[e]);

        float sum = 0.f;
        for (int e = 0; e < NEXP; e++) {
            float s = expf(lrow[e] - m);
            if (s < FTZ_MIN) s = 0.f;
            sum += s;
        }
        float inv_sum = 1.f / sum;

        float bv[TOPK]; int bi[TOPK];
        #pragma unroll
        for (int r = 0; r < TOPK; r++) { bv[r] = -FLT_MAX; bi[r] = 0; }

        for (int e = 0; e < NEXP; e++) {
            float s = expf(lrow[e] - m);
            if (s < FTZ_MIN) s = 0.f;
            float q = s * inv_sum;
            if (q < FTZ_MIN) q = 0.f;
            if (q > bv[TOPK - 1]) {
                int p = TOPK - 1;
                while (p > 0 && q > bv[p - 1]) {
                    bv[p] = bv[p - 1]; bi[p] = bi[p - 1]; p--;
                }
                bv[p] = q; bi[p] = e;
            }
        }
        s_max[t] = m;
        s_inv[t] = inv_sum;

        float den = 1e-20f;
        #pragma unroll
        for (int r = 0; r < TOPK; r++) den += bv[r];
        float inv = 1.f / den;

        const int token = base + t;
        const int part  = (t < t_split) ? 0 : 1;
        #pragma unroll
        for (int r = 0; r < TOPK; r++)
            out[(size_t)token * TOPK + r] = (float)bi[r];
        #pragma unroll
        for (int r = 0; r < TOPK; r++)
            out[(size_t)NTOK * TOPK + (size_t)token * TOPK + r] = bv[r] * inv;
        #pragma unroll
        for (int r = 0; r < TOPK; r++)
            atomicAdd(&s_cnt[part * NEXP + bi[r]], 1.f);
    }
    __syncthreads();

    // per-expert column sums, parallelized 4x: thread = (quarter q4, expert e)
    {
        const int e = tid & 63;
        const int q4 = tid >> 6;             // 0..3, tokens q4*27 .. q4*27+26
        const int t0 = q4 * 27;
        const int t1 = min(t0 + 27, nval);
        float cs0 = 0.f, cs1 = 0.f;
        for (int t = t0; t < t1; t++) {
            float s = expf(lg[t * LGS + e] - s_max[t]);
            if (s < FTZ_MIN) s = 0.f;
            float qq = s * s_inv[t];
            if (qq < FTZ_MIN) qq = 0.f;
            if (t < t_split) cs0 += qq; else cs1 += qq;
        }
        if (cs0 != 0.f) atomicAdd(&g_ssum[b0 * NEXP + e], cs0);
        if (t_split < nval && cs1 != 0.f)
            atomicAdd(&g_ssum[(b0 + 1) * NEXP + e], cs1);
        if (q4 == 0) {
            atomicAdd(&g_cnt[b0 * NEXP + e], s_cnt[e]);
            if (t_split < nval)
                atomicAdd(&g_cnt[(b0 + 1) * NEXP + e], s_cnt[NEXP + e]);
        }
    }

    // ---- fused finalize: last block computes aux, then resets globals ----
    __threadfence();
    __syncthreads();
    if (tid == 0)
        s_last = (atomicAdd(&g_done, 1u) == (unsigned)(NBLK - 1));
    __syncthreads();

    if (s_last) {
        // aux = mean_b sum_e (cnt/(SEQ*K/E)) * (ssum/SEQ)
        red[tid] = (g_cnt[tid] * (1.f / 512.f)) * (g_ssum[tid] * (1.f / 4096.f));
        __syncthreads();
        for (int s = 128; s > 0; s >>= 1) {
            if (tid < s) red[tid] += red[tid + s];
            __syncthreads();
        }
        if (tid == 0) out[2 * NTOK * TOPK] = red[0] * (1.f / BSZ);
        // reset for next graph replay
        g_cnt[tid] = 0.f;
        g_ssum[tid] = 0.f;
        if (tid == 0) g_done = 0u;
    }
}

extern "C" void kernel_launch(void* const* d_in, const int* in_sizes, int n_in,
                              void* d_out, int out_size) {
    const float* x    = (const float*)d_in[0];   // [4,4096,2048] f32
    const float* wgt  = (const float*)d_in[1];   // [64,2048]     f32
    const float* bias = (const float*)d_in[2];   // [64]          f32
    float* out = (float*)d_out;                  // [idx 131072][w 131072][aux 1]

    cudaFuncSetAttribute(gate_main, cudaFuncAttributeMaxDynamicSharedMemorySize,
                         SMEM_DYN);
    gate_main<<<NBLK, NTH, SMEM_DYN>>>(x, wgt, bias, out);
}